// round 2
// baseline (speedup 1.0000x reference)
#include <cuda_runtime.h>
#include <cuda_bf16.h>

// Problem dims (fixed by the dataset)
#define BB 4
#define TT_ 512
#define UU 128
#define DD 512
#define VV 512
#define MS (BB * TT_)   // 2048 speech rows
#define MT (BB * UU)    // 512 text rows

// Scratch (no cudaMalloc allowed): projected speech / text
__device__ float g_sp[MS * VV];   // speech @ W^T            (4 MB)
__device__ float g_tp[MT * VV];   // text   @ W^T + bias     (1 MB)

// ---------------------------------------------------------------------------
// GEMM: C[m, v] = sum_d A[m, d] * W[v, d]   (NT gemm, fp32)
// Tiles: BM=128, BN=64, BK=16; 256 threads; 8x4 per-thread micro-tile.
// blockIdx.y in [0,16): speech rows.  [16,20): text rows (bias added).
// ---------------------------------------------------------------------------
__global__ __launch_bounds__(256, 2)
void joint_gemm_kernel(const float* __restrict__ speech,
                       const float* __restrict__ text,
                       const float* __restrict__ Wm,
                       const float* __restrict__ bias)
{
    __shared__ float As[16][132];   // [k][m], padded
    __shared__ float Bs[16][68];    // [k][n]

    const int by = blockIdx.y;
    const int n0 = blockIdx.x * 64;

    const float* A;
    float* C;
    bool addb;
    if (by < 16) {
        A = speech + (size_t)by * 128 * DD;
        C = g_sp   + (size_t)by * 128 * VV;
        addb = false;
    } else {
        A = text + (size_t)(by - 16) * 128 * DD;
        C = g_tp + (size_t)(by - 16) * 128 * VV;
        addb = true;
    }

    const int tid = threadIdx.x;
    const int tm = tid >> 4;    // 0..15  -> rows tm*8 .. tm*8+7
    const int tn = tid & 15;    // 0..15  -> cols tn*4 .. tn*4+3

    float acc[8][4];
#pragma unroll
    for (int i = 0; i < 8; i++)
#pragma unroll
        for (int j = 0; j < 4; j++) acc[i][j] = 0.f;

    for (int k0 = 0; k0 < DD; k0 += 16) {
        // Load A tile: 128 rows x 16 k = 512 float4, 2 per thread
#pragma unroll
        for (int it = 0; it < 2; it++) {
            int s = tid + it * 256;
            int r = s >> 2;
            int c = s & 3;
            float4 v = *(const float4*)(A + (size_t)r * DD + k0 + c * 4);
            As[c * 4 + 0][r] = v.x;
            As[c * 4 + 1][r] = v.y;
            As[c * 4 + 2][r] = v.z;
            As[c * 4 + 3][r] = v.w;
        }
        // Load W tile: 64 rows x 16 k = 256 float4, 1 per thread
        {
            int r = tid >> 2;
            int c = tid & 3;
            float4 v = *(const float4*)(Wm + (size_t)(n0 + r) * DD + k0 + c * 4);
            Bs[c * 4 + 0][r] = v.x;
            Bs[c * 4 + 1][r] = v.y;
            Bs[c * 4 + 2][r] = v.z;
            Bs[c * 4 + 3][r] = v.w;
        }
        __syncthreads();

#pragma unroll
        for (int kk = 0; kk < 16; kk++) {
            float4 a0 = *(const float4*)&As[kk][tm * 8];
            float4 a1 = *(const float4*)&As[kk][tm * 8 + 4];
            float4 b0 = *(const float4*)&Bs[kk][tn * 4];
            float a[8] = {a0.x, a0.y, a0.z, a0.w, a1.x, a1.y, a1.z, a1.w};
            float bv[4] = {b0.x, b0.y, b0.z, b0.w};
#pragma unroll
            for (int i = 0; i < 8; i++)
#pragma unroll
                for (int j = 0; j < 4; j++) acc[i][j] += a[i] * bv[j];
        }
        __syncthreads();
    }

    // Epilogue
    float4 bb = make_float4(0.f, 0.f, 0.f, 0.f);
    if (addb) bb = *(const float4*)(bias + n0 + tn * 4);
#pragma unroll
    for (int i = 0; i < 8; i++) {
        int row = tm * 8 + i;
        float4 o;
        o.x = acc[i][0] + bb.x;
        o.y = acc[i][1] + bb.y;
        o.z = acc[i][2] + bb.z;
        o.w = acc[i][3] + bb.w;
        *(float4*)(C + (size_t)row * VV + n0 + tn * 4) = o;
    }
}

// ---------------------------------------------------------------------------
// Broadcast add: out[bt, u, v] = sp[bt, v] + tp[b*U + u, v].
// One block per (b,t) row; 128 threads; each thread owns 4 consecutive v.
// Pure DRAM-write-bound streaming; tp (1 MB) stays L2-resident.
// ---------------------------------------------------------------------------
__global__ __launch_bounds__(128)
void bcast_add_kernel(float* __restrict__ out)
{
    const int bt  = blockIdx.x;           // 0..2047
    const int b   = bt >> 9;              // bt / T
    const int tid = threadIdx.x;          // 0..127 -> v4 index

    const float4* sp4 = (const float4*)g_sp;
    const float4* tp4 = (const float4*)g_tp;

    float4 s = sp4[(size_t)bt * 128 + tid];

    const float4* tprow = tp4 + (size_t)b * UU * 128 + tid;
    float4* ob = (float4*)out + (size_t)bt * UU * 128 + tid;

#pragma unroll 4
    for (int u = 0; u < UU; u++) {
        float4 t = tprow[(size_t)u * 128];
        float4 r;
        r.x = s.x + t.x;
        r.y = s.y + t.y;
        r.z = s.z + t.z;
        r.w = s.w + t.w;
        ob[(size_t)u * 128] = r;
    }
}

// Lengths go after the logits block, CONVERTED TO THE OUTPUT DTYPE (float32).
__global__ void tail_copy_kernel(const int* __restrict__ slen,
                                 const int* __restrict__ tlen,
                                 float* __restrict__ out_f32)
{
    int i = threadIdx.x;   // 0..7
    size_t base = (size_t)BB * TT_ * UU * VV;
    if (i < 4) out_f32[base + i] = (float)slen[i];
    else       out_f32[base + i] = (float)tlen[i - 4];
}

extern "C" void kernel_launch(void* const* d_in, const int* in_sizes, int n_in,
                              void* d_out, int out_size)
{
    const float* speech = (const float*)d_in[0];
    const float* text   = (const float*)d_in[1];
    const float* Wm     = (const float*)d_in[2];
    const float* bias   = (const float*)d_in[3];
    const int*   slen   = (const int*)d_in[4];
    const int*   tlen   = (const int*)d_in[5];

    // Phase 1: both projections in one launch (160 blocks)
    dim3 ggrid(VV / 64, 20);
    joint_gemm_kernel<<<ggrid, 256>>>(speech, text, Wm, bias);

    // Phase 2: broadcast add (DRAM-write-bound)
    bcast_add_kernel<<<MS, 128>>>((float*)d_out);

    // Phase 3: trailing length outputs (as float, the flattened output dtype)
    tail_copy_kernel<<<1, 8>>>(slen, tlen, (float*)d_out);
}